// round 5
// baseline (speedup 1.0000x reference)
#include <cuda_runtime.h>
#include <math.h>

// Problem constants
#define B_   8
#define LQ_  1024
#define S_   256
#define D_   1024
#define H_   16
#define HD_  64
#define MQ_  (B_*LQ_)   // 8192
#define MKV_ (B_*S_)    // 2048

// ---------------------------------------------------------------------------
// Scratch (static device globals — no allocation in kernel_launch)
// ---------------------------------------------------------------------------
__device__ float g_q  [MQ_  * D_];
__device__ float g_k  [MKV_ * D_];
__device__ float g_v  [MKV_ * D_];
__device__ float g_ctx[MQ_  * D_];
__device__ float g_att[MQ_  * D_];
__device__ float g_mid[MQ_  * D_];
__device__ float g_ffn[MQ_  * D_];

// ---------------------------------------------------------------------------
// SGEMM NT: C[M,N] = act(A[M,K] * B[N,K]^T + bias)
// A is split at column ksplit between A0 (lda0) and A1 (lda1) to fuse concat.
// BM=BN=128, BK=16, 256 threads, 8x8 microtile (2x2 raked 64-blocks).
// ---------------------------------------------------------------------------
__global__ __launch_bounds__(256, 2)
void sgemm_nt(int M, int N, int K,
              const float* __restrict__ A0, int lda0,
              const float* __restrict__ A1, int lda1, int ksplit,
              const float* __restrict__ Bm, int ldb,
              const float* __restrict__ bias,
              float* __restrict__ C, int ldc, int act)
{
    __shared__ float As[16 * 128];
    __shared__ float Bs[16 * 128];

    const int tid = threadIdx.x;
    const int tx  = tid & 15;   // col group
    const int ty  = tid >> 4;   // row group
    const int m0  = blockIdx.y * 128;
    const int n0  = blockIdx.x * 128;

    float acc[8][8];
#pragma unroll
    for (int i = 0; i < 8; i++)
#pragma unroll
        for (int j = 0; j < 8; j++) acc[i][j] = 0.f;

    for (int k0 = 0; k0 < K; k0 += 16) {
        // --- load A tile (128 rows x 16 k), transposed into As[k][row]
        const bool side0 = (k0 < ksplit);
#pragma unroll
        for (int it = 0; it < 2; it++) {
            int e   = tid + it * 256;
            int row = e >> 2;
            int c4  = e & 3;
            int gr  = m0 + row;
            const float* ap = side0 ? (A0 + (size_t)gr * lda0 + k0)
                                    : (A1 + (size_t)gr * lda1 + (k0 - ksplit));
            float4 v = *(const float4*)(ap + c4 * 4);
            As[(c4 * 4 + 0) * 128 + row] = v.x;
            As[(c4 * 4 + 1) * 128 + row] = v.y;
            As[(c4 * 4 + 2) * 128 + row] = v.z;
            As[(c4 * 4 + 3) * 128 + row] = v.w;
        }
        // --- load B tile (128 n-rows x 16 k), transposed into Bs[k][n]
#pragma unroll
        for (int it = 0; it < 2; it++) {
            int e   = tid + it * 256;
            int row = e >> 2;
            int c4  = e & 3;
            int gn  = n0 + row;
            float4 v = *(const float4*)(Bm + (size_t)gn * ldb + k0 + c4 * 4);
            Bs[(c4 * 4 + 0) * 128 + row] = v.x;
            Bs[(c4 * 4 + 1) * 128 + row] = v.y;
            Bs[(c4 * 4 + 2) * 128 + row] = v.z;
            Bs[(c4 * 4 + 3) * 128 + row] = v.w;
        }
        __syncthreads();

#pragma unroll
        for (int kk = 0; kk < 16; kk++) {
            float ra[8], rb[8];
#pragma unroll
            for (int i = 0; i < 4; i++) {
                ra[i]     = As[kk * 128 +       ty * 4 + i];
                ra[4 + i] = As[kk * 128 + 64 +  ty * 4 + i];
            }
            float4 b0 = *(const float4*)&Bs[kk * 128 +      tx * 4];
            float4 b1 = *(const float4*)&Bs[kk * 128 + 64 + tx * 4];
            rb[0] = b0.x; rb[1] = b0.y; rb[2] = b0.z; rb[3] = b0.w;
            rb[4] = b1.x; rb[5] = b1.y; rb[6] = b1.z; rb[7] = b1.w;
#pragma unroll
            for (int i = 0; i < 8; i++)
#pragma unroll
                for (int j = 0; j < 8; j++)
                    acc[i][j] = fmaf(ra[i], rb[j], acc[i][j]);
        }
        __syncthreads();
    }

    // --- epilogue: bias + optional relu, vectorized store
#pragma unroll
    for (int ri = 0; ri < 2; ri++) {
#pragma unroll
        for (int i = 0; i < 4; i++) {
            int gr = m0 + ri * 64 + ty * 4 + i;
#pragma unroll
            for (int rj = 0; rj < 2; rj++) {
                int gc = n0 + rj * 64 + tx * 4;
                float4 bv = *(const float4*)&bias[gc];
                float4 o;
                o.x = acc[ri * 4 + i][rj * 4 + 0] + bv.x;
                o.y = acc[ri * 4 + i][rj * 4 + 1] + bv.y;
                o.z = acc[ri * 4 + i][rj * 4 + 2] + bv.z;
                o.w = acc[ri * 4 + i][rj * 4 + 3] + bv.w;
                if (act == 1) {
                    o.x = fmaxf(o.x, 0.f); o.y = fmaxf(o.y, 0.f);
                    o.z = fmaxf(o.z, 0.f); o.w = fmaxf(o.w, 0.f);
                }
                *(float4*)&C[(size_t)gr * ldc + gc] = o;
            }
        }
    }
}

// ---------------------------------------------------------------------------
// Attention: per (b, h, 64-q-row tile).
//   P = softmax(Q K^T / 8), ctx = P V.  S=256 keys, HD=64, fully in smem.
// smem: QsT[64d][64r] | KsT[64d][256s] | Vs[256s][64d] | P[256s][65(r pad)]
// ---------------------------------------------------------------------------
#define ATT_SMEM_FLOATS (4096 + 16384 + 16384 + 16640)
#define ATT_SMEM_BYTES  (ATT_SMEM_FLOATS * 4)

__global__ __launch_bounds__(256, 1)
void attn_kernel(const float* __restrict__ q, const float* __restrict__ k,
                 const float* __restrict__ v, float* __restrict__ ctx)
{
    extern __shared__ float sm[];
    float* QsT = sm;               // [d][r]  64*64
    float* KsT = QsT + 4096;       // [d][s]  64*256
    float* Vs  = KsT + 16384;      // [s][d]  256*64
    float* P   = Vs  + 16384;      // [s][r]  256*65 (pad)

    const int tid = threadIdx.x;
    const int l0  = blockIdx.x * 64;
    const int h   = blockIdx.y;
    const int b   = blockIdx.z;

    const float* qb = q + ((size_t)(b * LQ_ + l0)) * D_ + h * HD_;
    const float* kb = k + ((size_t)(b * S_)) * D_ + h * HD_;
    const float* vb = v + ((size_t)(b * S_)) * D_ + h * HD_;

    // loads (float4, coalesced)
    for (int e = tid; e < 64 * 16; e += 256) {           // Q tile
        int r = e >> 4, d4 = e & 15;
        float4 vv = *(const float4*)(qb + (size_t)r * D_ + d4 * 4);
        QsT[(d4 * 4 + 0) * 64 + r] = vv.x;
        QsT[(d4 * 4 + 1) * 64 + r] = vv.y;
        QsT[(d4 * 4 + 2) * 64 + r] = vv.z;
        QsT[(d4 * 4 + 3) * 64 + r] = vv.w;
    }
    for (int e = tid; e < 256 * 16; e += 256) {          // K tile
        int s = e >> 4, d4 = e & 15;
        float4 vv = *(const float4*)(kb + (size_t)s * D_ + d4 * 4);
        KsT[(d4 * 4 + 0) * 256 + s] = vv.x;
        KsT[(d4 * 4 + 1) * 256 + s] = vv.y;
        KsT[(d4 * 4 + 2) * 256 + s] = vv.z;
        KsT[(d4 * 4 + 3) * 256 + s] = vv.w;
    }
    for (int e = tid; e < 256 * 16; e += 256) {          // V tile
        int s = e >> 4, d4 = e & 15;
        *(float4*)&Vs[s * 64 + d4 * 4] =
            *(const float4*)(vb + (size_t)s * D_ + d4 * 4);
    }
    __syncthreads();

    // phase A: P[s][r] = 0.125 * sum_d Q[r][d] K[s][d]   (64x256x64 GEMM)
    {
        const int tx = tid & 31;   // s groups
        const int ty = tid >> 5;   // r groups (0..7)
        float acc[8][8];
#pragma unroll
        for (int i = 0; i < 8; i++)
#pragma unroll
            for (int j = 0; j < 8; j++) acc[i][j] = 0.f;

#pragma unroll 4
        for (int d = 0; d < 64; d++) {
            float ra[8], rb[8];
#pragma unroll
            for (int i = 0; i < 4; i++) {
                ra[i]     = QsT[d * 64 +      ty * 4 + i];
                ra[4 + i] = QsT[d * 64 + 32 + ty * 4 + i];
            }
            float4 b0 = *(const float4*)&KsT[d * 256 +       tx * 4];
            float4 b1 = *(const float4*)&KsT[d * 256 + 128 + tx * 4];
            rb[0] = b0.x; rb[1] = b0.y; rb[2] = b0.z; rb[3] = b0.w;
            rb[4] = b1.x; rb[5] = b1.y; rb[6] = b1.z; rb[7] = b1.w;
#pragma unroll
            for (int i = 0; i < 8; i++)
#pragma unroll
                for (int j = 0; j < 8; j++)
                    acc[i][j] = fmaf(ra[i], rb[j], acc[i][j]);
        }
#pragma unroll
        for (int ri = 0; ri < 2; ri++)
#pragma unroll
            for (int i = 0; i < 4; i++)
#pragma unroll
                for (int rj = 0; rj < 2; rj++)
#pragma unroll
                    for (int j = 0; j < 4; j++) {
                        int r = ri * 32 + ty * 4 + i;
                        int s = rj * 128 + tx * 4 + j;
                        P[s * 65 + r] = acc[ri * 4 + i][rj * 4 + j] * 0.125f;
                    }
    }
    __syncthreads();

    // phase B: softmax over s for each of 64 rows (8 rows per warp)
    {
        const int lane = tid & 31, w = tid >> 5;
#pragma unroll
        for (int rr = 0; rr < 8; rr++) {
            int r = w * 8 + rr;
            float vals[8];
            float m = -1e30f;
#pragma unroll
            for (int qq = 0; qq < 8; qq++) {
                vals[qq] = P[(lane + qq * 32) * 65 + r];
                m = fmaxf(m, vals[qq]);
            }
#pragma unroll
            for (int off = 16; off; off >>= 1)
                m = fmaxf(m, __shfl_xor_sync(0xffffffffu, m, off));
            float sum = 0.f;
#pragma unroll
            for (int qq = 0; qq < 8; qq++) {
                vals[qq] = __expf(vals[qq] - m);
                sum += vals[qq];
            }
#pragma unroll
            for (int off = 16; off; off >>= 1)
                sum += __shfl_xor_sync(0xffffffffu, sum, off);
            float inv = 1.f / sum;
#pragma unroll
            for (int qq = 0; qq < 8; qq++)
                P[(lane + qq * 32) * 65 + r] = vals[qq] * inv;
        }
    }
    __syncthreads();

    // phase C: ctx[r][d] = sum_s P[s][r] V[s][d]   (64x64x256)
    {
        const int tx = tid & 15;   // d group
        const int ty = tid >> 4;   // r group
        float acc[4][4];
#pragma unroll
        for (int i = 0; i < 4; i++)
#pragma unroll
            for (int j = 0; j < 4; j++) acc[i][j] = 0.f;

#pragma unroll 8
        for (int s = 0; s < 256; s++) {
            float rp[4];
#pragma unroll
            for (int i = 0; i < 4; i++) rp[i] = P[s * 65 + ty * 4 + i];
            float4 vv = *(const float4*)&Vs[s * 64 + tx * 4];
#pragma unroll
            for (int i = 0; i < 4; i++) {
                acc[i][0] = fmaf(rp[i], vv.x, acc[i][0]);
                acc[i][1] = fmaf(rp[i], vv.y, acc[i][1]);
                acc[i][2] = fmaf(rp[i], vv.z, acc[i][2]);
                acc[i][3] = fmaf(rp[i], vv.w, acc[i][3]);
            }
        }
        float* cb = ctx + ((size_t)(b * LQ_ + l0)) * D_ + h * HD_;
#pragma unroll
        for (int i = 0; i < 4; i++) {
            float4 o = make_float4(acc[i][0], acc[i][1], acc[i][2], acc[i][3]);
            *(float4*)(cb + (size_t)(ty * 4 + i) * D_ + tx * 4) = o;
        }
    }
}

// ---------------------------------------------------------------------------
// Epilogue: two layer-norms of ffn row + sigmoid box from attn_output[:4]
// one block (256 threads) per row; row = 1024 floats = one float4 per thread.
// ---------------------------------------------------------------------------
#define OUT_TGT 8388608u    // B*LQ*D
#define OUT_BOX 16777216u   // 2*B*LQ*D

__global__ __launch_bounds__(256)
void ln_box_kernel(const float* __restrict__ ffn, const float* __restrict__ attn,
                   const float* __restrict__ g1, const float* __restrict__ be1,
                   const float* __restrict__ g2, const float* __restrict__ be2,
                   float* __restrict__ out)
{
    __shared__ float red[8];
    __shared__ float bcast;
    const int row = blockIdx.x;
    const int tid = threadIdx.x;
    const int lane = tid & 31, w = tid >> 5;

    float4 x = ((const float4*)(ffn + (size_t)row * D_))[tid];

    // mean
    float s = x.x + x.y + x.z + x.w;
#pragma unroll
    for (int o = 16; o; o >>= 1) s += __shfl_xor_sync(0xffffffffu, s, o);
    if (lane == 0) red[w] = s;
    __syncthreads();
    if (w == 0) {
        float t = (lane < 8) ? red[lane] : 0.f;
#pragma unroll
        for (int o = 4; o; o >>= 1) t += __shfl_xor_sync(0xffffffffu, t, o);
        if (lane == 0) bcast = t * (1.f / 1024.f);
    }
    __syncthreads();
    const float mean = bcast;
    __syncthreads();

    float dx = x.x - mean, dy = x.y - mean, dz = x.z - mean, dw = x.w - mean;
    float sq = dx * dx + dy * dy + dz * dz + dw * dw;
#pragma unroll
    for (int o = 16; o; o >>= 1) sq += __shfl_xor_sync(0xffffffffu, sq, o);
    if (lane == 0) red[w] = sq;
    __syncthreads();
    if (w == 0) {
        float t = (lane < 8) ? red[lane] : 0.f;
#pragma unroll
        for (int o = 4; o; o >>= 1) t += __shfl_xor_sync(0xffffffffu, t, o);
        if (lane == 0) bcast = rsqrtf(t * (1.f / 1024.f) + 1e-5f);
    }
    __syncthreads();
    const float inv = bcast;

    float4 G1 = ((const float4*)g1)[tid];
    float4 B1 = ((const float4*)be1)[tid];
    float4 G2 = ((const float4*)g2)[tid];
    float4 B2 = ((const float4*)be2)[tid];

    float4 o1, o2;
    o1.x = dx * inv * G1.x + B1.x;  o2.x = dx * inv * G2.x + B2.x;
    o1.y = dy * inv * G1.y + B1.y;  o2.y = dy * inv * G2.y + B2.y;
    o1.z = dz * inv * G1.z + B1.z;  o2.z = dz * inv * G2.z + B2.z;
    o1.w = dw * inv * G1.w + B1.w;  o2.w = dw * inv * G2.w + B2.w;

    ((float4*)out)[(size_t)row * 256 + tid]             = o1;
    ((float4*)(out + OUT_TGT))[(size_t)row * 256 + tid] = o2;

    if (tid == 0) {
        const float* a = attn + (size_t)row * D_;
        float xc = 1.f / (1.f + __expf(-a[0]));
        float yc = 1.f / (1.f + __expf(-a[1]));
        float ww = 1.f / (1.f + __expf(-a[2]));
        float hh = 1.f / (1.f + __expf(-a[3]));
        float4 box = make_float4(xc - ww * 0.5f, yc - hh * 0.5f,
                                 xc + ww * 0.5f, yc + hh * 0.5f);
        *(float4*)(out + OUT_BOX + (size_t)row * 4) = box;
    }
}

// ---------------------------------------------------------------------------
// Launch
// ---------------------------------------------------------------------------
extern "C" void kernel_launch(void* const* d_in, const int* in_sizes, int n_in,
                              void* d_out, int out_size)
{
    const float* memory = (const float*)d_in[0];   // [B,LQ,512]
    const float* gaze   = (const float*)d_in[1];   // [B,LQ,512]
    const float* text   = (const float*)d_in[2];   // [B,S,D]
    const float* w_in   = (const float*)d_in[3];   // [3D,D]
    const float* b_in   = (const float*)d_in[4];   // [3D]
    const float* w_o    = (const float*)d_in[5];   // [D,D]
    const float* b_o    = (const float*)d_in[6];   // [D]
    const float* w1     = (const float*)d_in[7];
    const float* b1     = (const float*)d_in[8];
    const float* w2     = (const float*)d_in[9];
    const float* b2     = (const float*)d_in[10];
    const float* g1     = (const float*)d_in[11];
    const float* be1    = (const float*)d_in[12];
    const float* g2     = (const float*)d_in[13];
    const float* be2    = (const float*)d_in[14];
    float* out = (float*)d_out;

    float *Q, *Kb, *Vb, *CTX, *ATT, *MID, *FFN;
    cudaGetSymbolAddress((void**)&Q,   g_q);
    cudaGetSymbolAddress((void**)&Kb,  g_k);
    cudaGetSymbolAddress((void**)&Vb,  g_v);
    cudaGetSymbolAddress((void**)&CTX, g_ctx);
    cudaGetSymbolAddress((void**)&ATT, g_att);
    cudaGetSymbolAddress((void**)&MID, g_mid);
    cudaGetSymbolAddress((void**)&FFN, g_ffn);

    cudaFuncSetAttribute(attn_kernel,
                         cudaFuncAttributeMaxDynamicSharedMemorySize,
                         ATT_SMEM_BYTES);

    dim3 blk(256);
    dim3 gQ(D_ / 128, MQ_ / 128);    // (8, 64)
    dim3 gKV(D_ / 128, MKV_ / 128);  // (8, 16)

    // Q projection: fused concat(memory, gaze) @ wq^T + bq
    sgemm_nt<<<gQ, blk>>>(MQ_, D_, D_,
                          memory, 512, gaze, 512, 512,
                          w_in, D_, b_in, Q, D_, 0);
    // K projection
    sgemm_nt<<<gKV, blk>>>(MKV_, D_, D_,
                           text, D_, text, D_, D_,
                           w_in + (size_t)D_ * D_, D_, b_in + D_, Kb, D_, 0);
    // V projection
    sgemm_nt<<<gKV, blk>>>(MKV_, D_, D_,
                           text, D_, text, D_, D_,
                           w_in + 2 * (size_t)D_ * D_, D_, b_in + 2 * D_, Vb, D_, 0);

    // attention
    dim3 gA(LQ_ / 64, H_, B_);       // (16, 16, 8)
    attn_kernel<<<gA, blk, ATT_SMEM_BYTES>>>(Q, Kb, Vb, CTX);

    // output projection
    sgemm_nt<<<gQ, blk>>>(MQ_, D_, D_,
                          CTX, D_, CTX, D_, D_,
                          w_o, D_, b_o, ATT, D_, 0);
    // FFN layer 1 (relu)
    sgemm_nt<<<gQ, blk>>>(MQ_, D_, D_,
                          ATT, D_, ATT, D_, D_,
                          w1, D_, b1, MID, D_, 1);
    // FFN layer 2
    sgemm_nt<<<gQ, blk>>>(MQ_, D_, D_,
                          MID, D_, MID, D_, D_,
                          w2, D_, b2, FFN, D_, 0);

    // layer norms + box proposal
    ln_box_kernel<<<MQ_, blk>>>(FFN, ATT, g1, be1, g2, be2, out);
}

// round 6
// speedup vs baseline: 1.0014x; 1.0014x over previous
#include <cuda_runtime.h>
#include <math.h>

// Problem constants
#define B_   8
#define LQ_  1024
#define S_   256
#define D_   1024
#define H_   16
#define HD_  64
#define MQ_  (B_*LQ_)   // 8192
#define MKV_ (B_*S_)    // 2048

// ---------------------------------------------------------------------------
// Scratch (static device globals — no allocation in kernel_launch)
// ---------------------------------------------------------------------------
__device__ float g_q  [MQ_  * D_];
__device__ float g_k  [MKV_ * D_];
__device__ float g_v  [MKV_ * D_];
__device__ float g_ctx[MQ_  * D_];
__device__ float g_att[MQ_  * D_];
__device__ float g_mid[MQ_  * D_];
__device__ float g_ffn[MQ_  * D_];

// ---------------------------------------------------------------------------
// SGEMM NT: C[M,N] = act(A[M,K] * B[N,K]^T + bias)
// A is split at column ksplit between A0 (lda0) and A1 (lda1) to fuse concat.
// BM=BN=128, BK=16, 256 threads, 8x8 microtile (2x2 raked 64-blocks).
// ---------------------------------------------------------------------------
__global__ __launch_bounds__(256, 2)
void sgemm_nt(int M, int N, int K,
              const float* __restrict__ A0, int lda0,
              const float* __restrict__ A1, int lda1, int ksplit,
              const float* __restrict__ Bm, int ldb,
              const float* __restrict__ bias,
              float* __restrict__ C, int ldc, int act)
{
    __shared__ float As[16 * 128];
    __shared__ float Bs[16 * 128];

    const int tid = threadIdx.x;
    const int tx  = tid & 15;   // col group
    const int ty  = tid >> 4;   // row group
    const int m0  = blockIdx.y * 128;
    const int n0  = blockIdx.x * 128;

    float acc[8][8];
#pragma unroll
    for (int i = 0; i < 8; i++)
#pragma unroll
        for (int j = 0; j < 8; j++) acc[i][j] = 0.f;

    for (int k0 = 0; k0 < K; k0 += 16) {
        // --- load A tile (128 rows x 16 k), transposed into As[k][row]
        const bool side0 = (k0 < ksplit);
#pragma unroll
        for (int it = 0; it < 2; it++) {
            int e   = tid + it * 256;
            int row = e >> 2;
            int c4  = e & 3;
            int gr  = m0 + row;
            const float* ap = side0 ? (A0 + (size_t)gr * lda0 + k0)
                                    : (A1 + (size_t)gr * lda1 + (k0 - ksplit));
            float4 v = *(const float4*)(ap + c4 * 4);
            As[(c4 * 4 + 0) * 128 + row] = v.x;
            As[(c4 * 4 + 1) * 128 + row] = v.y;
            As[(c4 * 4 + 2) * 128 + row] = v.z;
            As[(c4 * 4 + 3) * 128 + row] = v.w;
        }
        // --- load B tile (128 n-rows x 16 k), transposed into Bs[k][n]
#pragma unroll
        for (int it = 0; it < 2; it++) {
            int e   = tid + it * 256;
            int row = e >> 2;
            int c4  = e & 3;
            int gn  = n0 + row;
            float4 v = *(const float4*)(Bm + (size_t)gn * ldb + k0 + c4 * 4);
            Bs[(c4 * 4 + 0) * 128 + row] = v.x;
            Bs[(c4 * 4 + 1) * 128 + row] = v.y;
            Bs[(c4 * 4 + 2) * 128 + row] = v.z;
            Bs[(c4 * 4 + 3) * 128 + row] = v.w;
        }
        __syncthreads();

#pragma unroll
        for (int kk = 0; kk < 16; kk++) {
            float ra[8], rb[8];
#pragma unroll
            for (int i = 0; i < 4; i++) {
                ra[i]     = As[kk * 128 +       ty * 4 + i];
                ra[4 + i] = As[kk * 128 + 64 +  ty * 4 + i];
            }
            float4 b0 = *(const float4*)&Bs[kk * 128 +      tx * 4];
            float4 b1 = *(const float4*)&Bs[kk * 128 + 64 + tx * 4];
            rb[0] = b0.x; rb[1] = b0.y; rb[2] = b0.z; rb[3] = b0.w;
            rb[4] = b1.x; rb[5] = b1.y; rb[6] = b1.z; rb[7] = b1.w;
#pragma unroll
            for (int i = 0; i < 8; i++)
#pragma unroll
                for (int j = 0; j < 8; j++)
                    acc[i][j] = fmaf(ra[i], rb[j], acc[i][j]);
        }
        __syncthreads();
    }

    // --- epilogue: bias + optional relu, vectorized store
#pragma unroll
    for (int ri = 0; ri < 2; ri++) {
#pragma unroll
        for (int i = 0; i < 4; i++) {
            int gr = m0 + ri * 64 + ty * 4 + i;
#pragma unroll
            for (int rj = 0; rj < 2; rj++) {
                int gc = n0 + rj * 64 + tx * 4;
                float4 bv = *(const float4*)&bias[gc];
                float4 o;
                o.x = acc[ri * 4 + i][rj * 4 + 0] + bv.x;
                o.y = acc[ri * 4 + i][rj * 4 + 1] + bv.y;
                o.z = acc[ri * 4 + i][rj * 4 + 2] + bv.z;
                o.w = acc[ri * 4 + i][rj * 4 + 3] + bv.w;
                if (act == 1) {
                    o.x = fmaxf(o.x, 0.f); o.y = fmaxf(o.y, 0.f);
                    o.z = fmaxf(o.z, 0.f); o.w = fmaxf(o.w, 0.f);
                }
                *(float4*)&C[(size_t)gr * ldc + gc] = o;
            }
        }
    }
}

// ---------------------------------------------------------------------------
// Attention: per (b, h, 64-q-row tile).
//   P = softmax(Q K^T / 8), ctx = P V.  S=256 keys, HD=64, fully in smem.
// smem: QsT[64d][64r] | KsT[64d][256s] | Vs[256s][64d] | P[256s][65(r pad)]
// ---------------------------------------------------------------------------
#define ATT_SMEM_FLOATS (4096 + 16384 + 16384 + 16640)
#define ATT_SMEM_BYTES  (ATT_SMEM_FLOATS * 4)

__global__ __launch_bounds__(256, 1)
void attn_kernel(const float* __restrict__ q, const float* __restrict__ k,
                 const float* __restrict__ v, float* __restrict__ ctx)
{
    extern __shared__ float sm[];
    float* QsT = sm;               // [d][r]  64*64
    float* KsT = QsT + 4096;       // [d][s]  64*256
    float* Vs  = KsT + 16384;      // [s][d]  256*64
    float* P   = Vs  + 16384;      // [s][r]  256*65 (pad)

    const int tid = threadIdx.x;
    const int l0  = blockIdx.x * 64;
    const int h   = blockIdx.y;
    const int b   = blockIdx.z;

    const float* qb = q + ((size_t)(b * LQ_ + l0)) * D_ + h * HD_;
    const float* kb = k + ((size_t)(b * S_)) * D_ + h * HD_;
    const float* vb = v + ((size_t)(b * S_)) * D_ + h * HD_;

    // loads (float4, coalesced)
    for (int e = tid; e < 64 * 16; e += 256) {           // Q tile
        int r = e >> 4, d4 = e & 15;
        float4 vv = *(const float4*)(qb + (size_t)r * D_ + d4 * 4);
        QsT[(d4 * 4 + 0) * 64 + r] = vv.x;
        QsT[(d4 * 4 + 1) * 64 + r] = vv.y;
        QsT[(d4 * 4 + 2) * 64 + r] = vv.z;
        QsT[(d4 * 4 + 3) * 64 + r] = vv.w;
    }
    for (int e = tid; e < 256 * 16; e += 256) {          // K tile
        int s = e >> 4, d4 = e & 15;
        float4 vv = *(const float4*)(kb + (size_t)s * D_ + d4 * 4);
        KsT[(d4 * 4 + 0) * 256 + s] = vv.x;
        KsT[(d4 * 4 + 1) * 256 + s] = vv.y;
        KsT[(d4 * 4 + 2) * 256 + s] = vv.z;
        KsT[(d4 * 4 + 3) * 256 + s] = vv.w;
    }
    for (int e = tid; e < 256 * 16; e += 256) {          // V tile
        int s = e >> 4, d4 = e & 15;
        *(float4*)&Vs[s * 64 + d4 * 4] =
            *(const float4*)(vb + (size_t)s * D_ + d4 * 4);
    }
    __syncthreads();

    // phase A: P[s][r] = 0.125 * sum_d Q[r][d] K[s][d]   (64x256x64 GEMM)
    {
        const int tx = tid & 31;   // s groups
        const int ty = tid >> 5;   // r groups (0..7)
        float acc[8][8];
#pragma unroll
        for (int i = 0; i < 8; i++)
#pragma unroll
            for (int j = 0; j < 8; j++) acc[i][j] = 0.f;

#pragma unroll 4
        for (int d = 0; d < 64; d++) {
            float ra[8], rb[8];
#pragma unroll
            for (int i = 0; i < 4; i++) {
                ra[i]     = QsT[d * 64 +      ty * 4 + i];
                ra[4 + i] = QsT[d * 64 + 32 + ty * 4 + i];
            }
            float4 b0 = *(const float4*)&KsT[d * 256 +       tx * 4];
            float4 b1 = *(const float4*)&KsT[d * 256 + 128 + tx * 4];
            rb[0] = b0.x; rb[1] = b0.y; rb[2] = b0.z; rb[3] = b0.w;
            rb[4] = b1.x; rb[5] = b1.y; rb[6] = b1.z; rb[7] = b1.w;
#pragma unroll
            for (int i = 0; i < 8; i++)
#pragma unroll
                for (int j = 0; j < 8; j++)
                    acc[i][j] = fmaf(ra[i], rb[j], acc[i][j]);
        }
#pragma unroll
        for (int ri = 0; ri < 2; ri++)
#pragma unroll
            for (int i = 0; i < 4; i++)
#pragma unroll
                for (int rj = 0; rj < 2; rj++)
#pragma unroll
                    for (int j = 0; j < 4; j++) {
                        int r = ri * 32 + ty * 4 + i;
                        int s = rj * 128 + tx * 4 + j;
                        P[s * 65 + r] = acc[ri * 4 + i][rj * 4 + j] * 0.125f;
                    }
    }
    __syncthreads();

    // phase B: softmax over s for each of 64 rows (8 rows per warp)
    {
        const int lane = tid & 31, w = tid >> 5;
#pragma unroll
        for (int rr = 0; rr < 8; rr++) {
            int r = w * 8 + rr;
            float vals[8];
            float m = -1e30f;
#pragma unroll
            for (int qq = 0; qq < 8; qq++) {
                vals[qq] = P[(lane + qq * 32) * 65 + r];
                m = fmaxf(m, vals[qq]);
            }
#pragma unroll
            for (int off = 16; off; off >>= 1)
                m = fmaxf(m, __shfl_xor_sync(0xffffffffu, m, off));
            float sum = 0.f;
#pragma unroll
            for (int qq = 0; qq < 8; qq++) {
                vals[qq] = __expf(vals[qq] - m);
                sum += vals[qq];
            }
#pragma unroll
            for (int off = 16; off; off >>= 1)
                sum += __shfl_xor_sync(0xffffffffu, sum, off);
            float inv = 1.f / sum;
#pragma unroll
            for (int qq = 0; qq < 8; qq++)
                P[(lane + qq * 32) * 65 + r] = vals[qq] * inv;
        }
    }
    __syncthreads();

    // phase C: ctx[r][d] = sum_s P[s][r] V[s][d]   (64x64x256)
    {
        const int tx = tid & 15;   // d group
        const int ty = tid >> 4;   // r group
        float acc[4][4];
#pragma unroll
        for (int i = 0; i < 4; i++)
#pragma unroll
            for (int j = 0; j < 4; j++) acc[i][j] = 0.f;

#pragma unroll 8
        for (int s = 0; s < 256; s++) {
            float rp[4];
#pragma unroll
            for (int i = 0; i < 4; i++) rp[i] = P[s * 65 + ty * 4 + i];
            float4 vv = *(const float4*)&Vs[s * 64 + tx * 4];
#pragma unroll
            for (int i = 0; i < 4; i++) {
                acc[i][0] = fmaf(rp[i], vv.x, acc[i][0]);
                acc[i][1] = fmaf(rp[i], vv.y, acc[i][1]);
                acc[i][2] = fmaf(rp[i], vv.z, acc[i][2]);
                acc[i][3] = fmaf(rp[i], vv.w, acc[i][3]);
            }
        }
        float* cb = ctx + ((size_t)(b * LQ_ + l0)) * D_ + h * HD_;
#pragma unroll
        for (int i = 0; i < 4; i++) {
            float4 o = make_float4(acc[i][0], acc[i][1], acc[i][2], acc[i][3]);
            *(float4*)(cb + (size_t)(ty * 4 + i) * D_ + tx * 4) = o;
        }
    }
}

// ---------------------------------------------------------------------------
// Epilogue: two layer-norms of ffn row + sigmoid box from attn_output[:4]
// one block (256 threads) per row; row = 1024 floats = one float4 per thread.
// ---------------------------------------------------------------------------
#define OUT_TGT 8388608u    // B*LQ*D
#define OUT_BOX 16777216u   // 2*B*LQ*D

__global__ __launch_bounds__(256)
void ln_box_kernel(const float* __restrict__ ffn, const float* __restrict__ attn,
                   const float* __restrict__ g1, const float* __restrict__ be1,
                   const float* __restrict__ g2, const float* __restrict__ be2,
                   float* __restrict__ out)
{
    __shared__ float red[8];
    __shared__ float bcast;
    const int row = blockIdx.x;
    const int tid = threadIdx.x;
    const int lane = tid & 31, w = tid >> 5;

    float4 x = ((const float4*)(ffn + (size_t)row * D_))[tid];

    // mean
    float s = x.x + x.y + x.z + x.w;
#pragma unroll
    for (int o = 16; o; o >>= 1) s += __shfl_xor_sync(0xffffffffu, s, o);
    if (lane == 0) red[w] = s;
    __syncthreads();
    if (w == 0) {
        float t = (lane < 8) ? red[lane] : 0.f;
#pragma unroll
        for (int o = 4; o; o >>= 1) t += __shfl_xor_sync(0xffffffffu, t, o);
        if (lane == 0) bcast = t * (1.f / 1024.f);
    }
    __syncthreads();
    const float mean = bcast;
    __syncthreads();

    float dx = x.x - mean, dy = x.y - mean, dz = x.z - mean, dw = x.w - mean;
    float sq = dx * dx + dy * dy + dz * dz + dw * dw;
#pragma unroll
    for (int o = 16; o; o >>= 1) sq += __shfl_xor_sync(0xffffffffu, sq, o);
    if (lane == 0) red[w] = sq;
    __syncthreads();
    if (w == 0) {
        float t = (lane < 8) ? red[lane] : 0.f;
#pragma unroll
        for (int o = 4; o; o >>= 1) t += __shfl_xor_sync(0xffffffffu, t, o);
        if (lane == 0) bcast = rsqrtf(t * (1.f / 1024.f) + 1e-5f);
    }
    __syncthreads();
    const float inv = bcast;

    float4 G1 = ((const float4*)g1)[tid];
    float4 B1 = ((const float4*)be1)[tid];
    float4 G2 = ((const float4*)g2)[tid];
    float4 B2 = ((const float4*)be2)[tid];

    float4 o1, o2;
    o1.x = dx * inv * G1.x + B1.x;  o2.x = dx * inv * G2.x + B2.x;
    o1.y = dy * inv * G1.y + B1.y;  o2.y = dy * inv * G2.y + B2.y;
    o1.z = dz * inv * G1.z + B1.z;  o2.z = dz * inv * G2.z + B2.z;
    o1.w = dw * inv * G1.w + B1.w;  o2.w = dw * inv * G2.w + B2.w;

    ((float4*)out)[(size_t)row * 256 + tid]             = o1;
    ((float4*)(out + OUT_TGT))[(size_t)row * 256 + tid] = o2;

    if (tid == 0) {
        const float* a = attn + (size_t)row * D_;
        float xc = 1.f / (1.f + __expf(-a[0]));
        float yc = 1.f / (1.f + __expf(-a[1]));
        float ww = 1.f / (1.f + __expf(-a[2]));
        float hh = 1.f / (1.f + __expf(-a[3]));
        float4 box = make_float4(xc - ww * 0.5f, yc - hh * 0.5f,
                                 xc + ww * 0.5f, yc + hh * 0.5f);
        *(float4*)(out + OUT_BOX + (size_t)row * 4) = box;
    }
}

// ---------------------------------------------------------------------------
// Launch
// ---------------------------------------------------------------------------
extern "C" void kernel_launch(void* const* d_in, const int* in_sizes, int n_in,
                              void* d_out, int out_size)
{
    const float* memory = (const float*)d_in[0];   // [B,LQ,512]
    const float* gaze   = (const float*)d_in[1];   // [B,LQ,512]
    const float* text   = (const float*)d_in[2];   // [B,S,D]
    const float* w_in   = (const float*)d_in[3];   // [3D,D]
    const float* b_in   = (const float*)d_in[4];   // [3D]
    const float* w_o    = (const float*)d_in[5];   // [D,D]
    const float* b_o    = (const float*)d_in[6];   // [D]
    const float* w1     = (const float*)d_in[7];
    const float* b1     = (const float*)d_in[8];
    const float* w2     = (const float*)d_in[9];
    const float* b2     = (const float*)d_in[10];
    const float* g1     = (const float*)d_in[11];
    const float* be1    = (const float*)d_in[12];
    const float* g2     = (const float*)d_in[13];
    const float* be2    = (const float*)d_in[14];
    float* out = (float*)d_out;

    float *Q, *Kb, *Vb, *CTX, *ATT, *MID, *FFN;
    cudaGetSymbolAddress((void**)&Q,   g_q);
    cudaGetSymbolAddress((void**)&Kb,  g_k);
    cudaGetSymbolAddress((void**)&Vb,  g_v);
    cudaGetSymbolAddress((void**)&CTX, g_ctx);
    cudaGetSymbolAddress((void**)&ATT, g_att);
    cudaGetSymbolAddress((void**)&MID, g_mid);
    cudaGetSymbolAddress((void**)&FFN, g_ffn);

    cudaFuncSetAttribute(attn_kernel,
                         cudaFuncAttributeMaxDynamicSharedMemorySize,
                         ATT_SMEM_BYTES);

    dim3 blk(256);
    dim3 gQ(D_ / 128, MQ_ / 128);    // (8, 64)
    dim3 gKV(D_ / 128, MKV_ / 128);  // (8, 16)

    // Q projection: fused concat(memory, gaze) @ wq^T + bq
    sgemm_nt<<<gQ, blk>>>(MQ_, D_, D_,
                          memory, 512, gaze, 512, 512,
                          w_in, D_, b_in, Q, D_, 0);
    // K projection
    sgemm_nt<<<gKV, blk>>>(MKV_, D_, D_,
                           text, D_, text, D_, D_,
                           w_in + (size_t)D_ * D_, D_, b_in + D_, Kb, D_, 0);
    // V projection
    sgemm_nt<<<gKV, blk>>>(MKV_, D_, D_,
                           text, D_, text, D_, D_,
                           w_in + 2 * (size_t)D_ * D_, D_, b_in + 2 * D_, Vb, D_, 0);

    // attention
    dim3 gA(LQ_ / 64, H_, B_);       // (16, 16, 8)
    attn_kernel<<<gA, blk, ATT_SMEM_BYTES>>>(Q, Kb, Vb, CTX);

    // output projection
    sgemm_nt<<<gQ, blk>>>(MQ_, D_, D_,
                          CTX, D_, CTX, D_, D_,
                          w_o, D_, b_o, ATT, D_, 0);
    // FFN layer 1 (relu)
    sgemm_nt<<<gQ, blk>>>(MQ_, D_, D_,
                          ATT, D_, ATT, D_, D_,
                          w1, D_, b1, MID, D_, 1);
    // FFN layer 2
    sgemm_nt<<<gQ, blk>>>(MQ_, D_, D_,
                          MID, D_, MID, D_, D_,
                          w2, D_, b2, FFN, D_, 0);

    // layer norms + box proposal
    ln_box_kernel<<<MQ_, blk>>>(FFN, ATT, g1, be1, g2, be2, out);
}